// round 11
// baseline (speedup 1.0000x reference)
#include <cuda_runtime.h>
#include <math.h>

#define NS     64
#define HID    20
#define HDIM   1280
#define BATCH  16384
#define MROWS  8
#define T      512
#define PSTR   1284
#define P6STR  68
#define LVL    806400          // 2016*400 floats per level

typedef unsigned long long ull;

// Chunk-major scatter weights (best measured layout):
//   slab si (nt=(63-si)*20 targets): float4 at [k*nt + j] = W[j][4k..4k+3]
__device__ float g_Ws4[4 * LVL];
__device__ float g_W1s[2016 * 20];      // fc1 scalar, j-major
__device__ float g_W6s[2016 * 20];      // fc6 chunk-major: (k, t) float4
__device__ float g_Wd [64 * 2020];      // diag per si: [lv*400 + ci*20 + c], fc6 at 2000

__device__ __forceinline__ int slab_off1(int si) { return 63 * si - (si * (si - 1)) / 2; }

__global__ void prep_scatter(const float* __restrict__ W1, const float* __restrict__ W2,
                             const float* __restrict__ W3, const float* __restrict__ W4,
                             const float* __restrict__ W5, const float* __restrict__ W6)
{
    const int si = blockIdx.x, what = blockIdx.y;
    const int nso1 = 63 - si;
    const int nt = nso1 * 20;
    if (what < 4) {
        const float* W = (what == 0) ? W2 : (what == 1) ? W3 : (what == 2) ? W4 : W5;
        float* dst = g_Ws4 + (size_t)what * LVL + (size_t)slab_off1(si) * 400;
        const int cnt = nso1 * 400;
        for (int t = threadIdx.x; t < cnt; t += blockDim.x) {
            int m = t & 3, q = t >> 2;
            int j = q % nt, k = q / nt;
            int so = si + 1 + j / 20, c = j % 20, ci = 4 * k + m;
            dst[t] = W[(size_t)(c * NS + so) * HDIM + ci * NS + si];
        }
    } else if (what == 4) {
        float* d1 = g_W1s + (size_t)slab_off1(si) * 20;
        for (int t = threadIdx.x; t < nt; t += blockDim.x) {
            int so = si + 1 + t / 20, c = t % 20;
            d1[t] = W1[(size_t)(c * NS + so) * NS + si];
        }
        float* dd = g_Wd + (size_t)si * 2020;
        for (int t = threadIdx.x; t < 2020; t += blockDim.x) {
            if (t < 1600) {
                int lv = t / 400, rem = t - lv * 400;
                int ci = rem / 20, c = rem - ci * 20;
                const float* W = (lv == 0) ? W2 : (lv == 1) ? W3 : (lv == 2) ? W4 : W5;
                dd[t] = W[(size_t)(c * NS + si) * HDIM + ci * NS + si];
            } else if (t < 2000) {
                dd[t] = 0.0f;
            } else {
                dd[t] = W6[(size_t)si * HDIM + (t - 2000) * NS + si];
            }
        }
    } else {
        float* d6 = g_W6s + (size_t)slab_off1(si) * 20;
        const int cnt = nso1 * 20;
        for (int t = threadIdx.x; t < cnt; t += blockDim.x) {
            int m = t & 3, q = t >> 2;
            int tt = q % nso1, k = q / nso1;
            int so = si + 1 + tt, ci = 4 * k + m;
            d6[t] = W6[(size_t)so * HDIM + ci * NS + si];
        }
    }
}

__device__ __forceinline__ ull ffma2(ull a, ull b, ull c)
{
    ull d;
    asm("fma.rn.f32x2 %0, %1, %2, %3;" : "=l"(d) : "l"(a), "l"(b), "l"(c));
    return d;
}
__device__ __forceinline__ ull pack2(float lo, float hi)
{
    ull v;
    asm("mov.b64 %0, {%1, %2};" : "=l"(v) : "f"(lo), "f"(hi));
    return v;
}
__device__ __forceinline__ float hsum2(ull v)
{
    float lo, hi;
    asm("mov.b64 {%0, %1}, %2;" : "=f"(lo), "=f"(hi) : "l"(v));
    return lo + hi;
}
__device__ __forceinline__ float sigmoidf(float x) { return 1.0f / (1.0f + expf(-x)); }

#define BAR_DIAG() asm volatile("bar.sync 1, 160;" ::: "memory")

__global__ void __launch_bounds__(T, 1)
net_kernel(const float* __restrict__ u, float* __restrict__ out)
{
    extern __shared__ float sm[];
    float* pre  = sm;                       // [5][8][PSTR]  (16B aligned; PSTR%4==0)
    float* pre6 = pre + 5 * MROWS * PSTR;   // [8][P6STR]
    float* hbt  = pre6 + MROWS * P6STR;     // [5][8][20]
    float* usm  = hbt + 5 * 160;            // [8][64]
    float* wd   = usm + 512;                // [2020]
    ull*   svd  = (ull*)(wd + 2020);        // [8] dup-packed sample (s,s)

    const int tid = threadIdx.x;
    const int pair = tid & 3, jq = tid >> 2;     // jq in 0..127 (quad lane)
    const int r0 = 2 * pair, r1 = r0 + 1;

    for (int k = tid; k < 5 * MROWS * PSTR; k += T) pre[k] = 0.0f;
    for (int k = tid; k < MROWS * P6STR; k += T) pre6[k] = 0.0f;
    {
        int ii = tid >> 3, rr = tid & 7;
        usm[rr * NS + ii] = u[(size_t)ii * BATCH + (size_t)blockIdx.x * MROWS + rr];
    }
    for (int k = tid; k < 2020; k += T) wd[k] = g_Wd[k];
    __syncthreads();

    for (int i = 0; i < NS; ++i) {
        // ===== diagonal chain: 160 threads =====
        if (tid < 160) {
            const int dr = tid / 20, dc = tid - (tid / 20) * 20;
            hbt[dr * 20 + dc] = sigmoidf(pre[dr * PSTR + i * HID + dc]);
            BAR_DIAG();
            #pragma unroll 1
            for (int lv = 0; lv < 4; ++lv) {
                float acc = pre[((lv + 1) * MROWS + dr) * PSTR + i * HID + dc];
                float acc2 = 0.0f;
                const float* w  = wd + lv * 400 + dc;
                const float* hh = hbt + lv * 160 + dr * 20;
                #pragma unroll
                for (int ci = 0; ci < 10; ++ci) {
                    acc  = fmaf(w[(2 * ci)     * 20], hh[2 * ci],     acc);
                    acc2 = fmaf(w[(2 * ci + 1) * 20], hh[2 * ci + 1], acc2);
                }
                hbt[(lv + 1) * 160 + dr * 20 + dc] = sigmoidf(acc + acc2);
                BAR_DIAG();
            }
            if (tid < MROWS) {                           // fc6 diag + sample
                float acc = pre6[tid * P6STR + i];
                const float* hh = hbt + 4 * 160 + tid * 20;
                #pragma unroll
                for (int ci = 0; ci < 20; ++ci) acc = fmaf(wd[2000 + ci], hh[ci], acc);
                float x = sigmoidf(acc);
                out[((size_t)blockIdx.x * MROWS + tid) * NS + i] = x;
                float s = (x >= usm[tid * NS + i]) ? 1.0f : -1.0f;
                svd[tid] = pack2(s, s);
            }
        }
        __syncthreads();

        // ===== scatter phase =====
        if (i < 63) {
            const int nso1 = 63 - i;
            const int nt = nso1 * HID;                   // multiple of 4
            const int tbase = (i + 1) * HID;             // multiple of 4
            const size_t soff = (size_t)slab_off1(i);

            // fc2..fc5 — 4 targets per iteration, float4 dst RMW (2 LDS.128 + 2 STS.128)
            #pragma unroll 1
            for (int l = 0; l < 4; ++l) {
                const float* wb = g_Ws4 + (size_t)l * LVL + soff * 400;
                float* prl = pre + (size_t)(l + 1) * MROWS * PSTR + tbase;
                ulonglong2 h0[5], h1[5];
                {
                    const ulonglong2* p0 = (const ulonglong2*)(hbt + l * 160 + r0 * 20);
                    const ulonglong2* p1 = (const ulonglong2*)(hbt + l * 160 + r1 * 20);
                    #pragma unroll
                    for (int q = 0; q < 5; ++q) { h0[q] = p0[q]; h1[q] = p1[q]; }
                }
                #pragma unroll 1
                for (int jb = 4 * jq; jb < nt; jb += 512) {
                    float4 dA = *(float4*)(prl + r0 * PSTR + jb);
                    float4 dB = *(float4*)(prl + r1 * PSTR + jb);
                    ulonglong2 w0[5], w1[5];
                    // --- targets jb, jb+1 ---
                    #pragma unroll
                    for (int k = 0; k < 5; ++k) {
                        w0[k] = *(const ulonglong2*)(wb + ((size_t)k * nt + jb)     * 4);
                        w1[k] = *(const ulonglong2*)(wb + ((size_t)k * nt + jb + 1) * 4);
                    }
                    ull a00 = 0ull, a01 = 0ull, a10 = 0ull, a11 = 0ull;
                    #pragma unroll
                    for (int k = 0; k < 5; ++k) {
                        a00 = ffma2(w0[k].x, h0[k].x, a00); a00 = ffma2(w0[k].y, h0[k].y, a00);
                        a01 = ffma2(w1[k].x, h0[k].x, a01); a01 = ffma2(w1[k].y, h0[k].y, a01);
                        a10 = ffma2(w0[k].x, h1[k].x, a10); a10 = ffma2(w0[k].y, h1[k].y, a10);
                        a11 = ffma2(w1[k].x, h1[k].x, a11); a11 = ffma2(w1[k].y, h1[k].y, a11);
                    }
                    float rA0 = hsum2(a00), rA1 = hsum2(a01);
                    float rB0 = hsum2(a10), rB1 = hsum2(a11);
                    // --- targets jb+2, jb+3 (reuse w buffers) ---
                    #pragma unroll
                    for (int k = 0; k < 5; ++k) {
                        w0[k] = *(const ulonglong2*)(wb + ((size_t)k * nt + jb + 2) * 4);
                        w1[k] = *(const ulonglong2*)(wb + ((size_t)k * nt + jb + 3) * 4);
                    }
                    a00 = 0ull; a01 = 0ull; a10 = 0ull; a11 = 0ull;
                    #pragma unroll
                    for (int k = 0; k < 5; ++k) {
                        a00 = ffma2(w0[k].x, h0[k].x, a00); a00 = ffma2(w0[k].y, h0[k].y, a00);
                        a01 = ffma2(w1[k].x, h0[k].x, a01); a01 = ffma2(w1[k].y, h0[k].y, a01);
                        a10 = ffma2(w0[k].x, h1[k].x, a10); a10 = ffma2(w0[k].y, h1[k].y, a10);
                        a11 = ffma2(w1[k].x, h1[k].x, a11); a11 = ffma2(w1[k].y, h1[k].y, a11);
                    }
                    float4 oA = make_float4(dA.x + rA0, dA.y + rA1,
                                            dA.z + hsum2(a00), dA.w + hsum2(a01));
                    float4 oB = make_float4(dB.x + rB0, dB.y + rB1,
                                            dB.z + hsum2(a10), dB.w + hsum2(a11));
                    *(float4*)(prl + r0 * PSTR + jb) = oA;
                    *(float4*)(prl + r1 * PSTR + jb) = oB;
                }
            }
            // fc6 (single round, lanes jq < nso1) — unchanged
            if (jq < nso1) {
                const float* wb6 = g_W6s + soff * 20;
                const ulonglong2* hp0 = (const ulonglong2*)(hbt + 4 * 160 + r0 * 20);
                const ulonglong2* hp1 = (const ulonglong2*)(hbt + 4 * 160 + r1 * 20);
                float* d0p = pre6 + r0 * P6STR + (i + 1 + jq);
                float* d1p = pre6 + r1 * P6STR + (i + 1 + jq);
                float dd0 = *d0p, dd1 = *d1p;
                ull a0 = 0ull, a1 = 0ull;
                #pragma unroll
                for (int k = 0; k < 5; ++k) {
                    ulonglong2 wv = *(const ulonglong2*)(wb6 + ((size_t)k * nso1 + jq) * 4);
                    ulonglong2 h0v = hp0[k], h1v = hp1[k];
                    a0 = ffma2(wv.x, h0v.x, a0); a0 = ffma2(wv.y, h0v.y, a0);
                    a1 = ffma2(wv.x, h1v.x, a1); a1 = ffma2(wv.y, h1v.y, a1);
                }
                *d0p = hsum2(a0) + dd0;
                *d1p = hsum2(a1) + dd1;
            }
            // fc1 rank-1 — quad-vectorized: 1 LDG.128 + 2 LDS.128 + 2 STS.128 per iter
            {
                const float* wb1 = g_W1s + soff * 20;
                float* p1 = pre + tbase;
                const ull s0 = svd[r0], s1 = svd[r1];
                #pragma unroll 1
                for (int jb = 4 * jq; jb < nt; jb += 512) {
                    ulonglong2 wv = *(const ulonglong2*)(wb1 + jb);   // (wj0,wj1),(wj2,wj3)
                    ulonglong2 d0 = *(ulonglong2*)(p1 + r0 * PSTR + jb);
                    ulonglong2 d1 = *(ulonglong2*)(p1 + r1 * PSTR + jb);
                    d0.x = ffma2(wv.x, s0, d0.x); d0.y = ffma2(wv.y, s0, d0.y);
                    d1.x = ffma2(wv.x, s1, d1.x); d1.y = ffma2(wv.y, s1, d1.y);
                    *(ulonglong2*)(p1 + r0 * PSTR + jb) = d0;
                    *(ulonglong2*)(p1 + r1 * PSTR + jb) = d1;
                }
            }
            // prefetch next step's diag weights
            {
                const float* src = g_Wd + (size_t)(i + 1) * 2020;
                for (int k = tid; k < 2020; k += T) wd[k] = src[k];
            }
        }
        __syncthreads();
    }
}

extern "C" void kernel_launch(void* const* d_in, const int* in_sizes, int n_in,
                              void* d_out, int out_size)
{
    (void)in_sizes; (void)n_in; (void)out_size;
    const float* u  = (const float*)d_in[1];
    const float* W1 = (const float*)d_in[2];
    const float* W2 = (const float*)d_in[3];
    const float* W3 = (const float*)d_in[4];
    const float* W4 = (const float*)d_in[5];
    const float* W5 = (const float*)d_in[6];
    const float* W6 = (const float*)d_in[7];
    float* out = (float*)d_out;

    dim3 pg(64, 6);
    prep_scatter<<<pg, 256>>>(W1, W2, W3, W4, W5, W6);

    const int smem_bytes = (5 * MROWS * PSTR + MROWS * P6STR + 5 * 160
                            + 512 + 2020 + 16) * (int)sizeof(float);   // ~221 KB
    cudaFuncSetAttribute(net_kernel, cudaFuncAttributeMaxDynamicSharedMemorySize, smem_bytes);
    net_kernel<<<BATCH / MROWS, T, smem_bytes>>>(u, out);
}

// round 12
// speedup vs baseline: 1.1865x; 1.1865x over previous
#include <cuda_runtime.h>
#include <math.h>

#define NS     64
#define HID    20
#define HDIM   1280
#define BATCH  16384
#define MROWS  8
#define T      512
#define NJW    32              // j-lanes per level (4 warps x 8 groups)
#define PSTR   1284
#define P6STR  68
#define LVL    806400          // 2016*400 floats per level

typedef unsigned long long ull;

// Chunk-major scatter weights (best measured layout):
//   slab si (nt=(63-si)*20 targets): float4 at [k*nt + j] = W[j][4k..4k+3]
__device__ float g_Ws4[4 * LVL];
__device__ float g_W1s[2016 * 20];      // fc1 scalar, j-major
__device__ float g_W6s[2016 * 20];      // fc6 chunk-major: (k, t) float4
__device__ float g_Wd [64 * 2020];      // diag per si: [lv*400 + ci*20 + c], fc6 at 2000

__device__ __forceinline__ int slab_off1(int si) { return 63 * si - (si * (si - 1)) / 2; }

__global__ void prep_scatter(const float* __restrict__ W1, const float* __restrict__ W2,
                             const float* __restrict__ W3, const float* __restrict__ W4,
                             const float* __restrict__ W5, const float* __restrict__ W6)
{
    const int si = blockIdx.x, what = blockIdx.y;
    const int nso1 = 63 - si;
    const int nt = nso1 * 20;
    if (what < 4) {
        const float* W = (what == 0) ? W2 : (what == 1) ? W3 : (what == 2) ? W4 : W5;
        float* dst = g_Ws4 + (size_t)what * LVL + (size_t)slab_off1(si) * 400;
        const int cnt = nso1 * 400;
        for (int t = threadIdx.x; t < cnt; t += blockDim.x) {
            int m = t & 3, q = t >> 2;
            int j = q % nt, k = q / nt;
            int so = si + 1 + j / 20, c = j % 20, ci = 4 * k + m;
            dst[t] = W[(size_t)(c * NS + so) * HDIM + ci * NS + si];
        }
    } else if (what == 4) {
        float* d1 = g_W1s + (size_t)slab_off1(si) * 20;
        for (int t = threadIdx.x; t < nt; t += blockDim.x) {
            int so = si + 1 + t / 20, c = t % 20;
            d1[t] = W1[(size_t)(c * NS + so) * NS + si];
        }
        float* dd = g_Wd + (size_t)si * 2020;
        for (int t = threadIdx.x; t < 2020; t += blockDim.x) {
            if (t < 1600) {
                int lv = t / 400, rem = t - lv * 400;
                int ci = rem / 20, c = rem - ci * 20;
                const float* W = (lv == 0) ? W2 : (lv == 1) ? W3 : (lv == 2) ? W4 : W5;
                dd[t] = W[(size_t)(c * NS + si) * HDIM + ci * NS + si];
            } else if (t < 2000) {
                dd[t] = 0.0f;
            } else {
                dd[t] = W6[(size_t)si * HDIM + (t - 2000) * NS + si];
            }
        }
    } else {
        float* d6 = g_W6s + (size_t)slab_off1(si) * 20;
        const int cnt = nso1 * 20;
        for (int t = threadIdx.x; t < cnt; t += blockDim.x) {
            int m = t & 3, q = t >> 2;
            int tt = q % nso1, k = q / nso1;
            int so = si + 1 + tt, ci = 4 * k + m;
            d6[t] = W6[(size_t)so * HDIM + ci * NS + si];
        }
    }
}

__device__ __forceinline__ ull ffma2(ull a, ull b, ull c)
{
    ull d;
    asm("fma.rn.f32x2 %0, %1, %2, %3;" : "=l"(d) : "l"(a), "l"(b), "l"(c));
    return d;
}
__device__ __forceinline__ ull pack2(float lo, float hi)
{
    ull v;
    asm("mov.b64 %0, {%1, %2};" : "=l"(v) : "f"(lo), "f"(hi));
    return v;
}
__device__ __forceinline__ float hsum2(ull v)
{
    float lo, hi;
    asm("mov.b64 {%0, %1}, %2;" : "=f"(lo), "=f"(hi) : "l"(v));
    return lo + hi;
}
__device__ __forceinline__ float sigmoidf(float x) { return 1.0f / (1.0f + expf(-x)); }

#define BAR_DIAG() asm volatile("bar.sync 1, 160;" ::: "memory")

// pipeline stage: load 5 weight chunks AND the two dst accumulators for target j
#define WLOAD(W, D0, D1, j) do {                                                \
    (W)[0] = *(const ulonglong2*)(wb + ((size_t)0 * nt + (j)) * 4);             \
    (W)[1] = *(const ulonglong2*)(wb + ((size_t)1 * nt + (j)) * 4);             \
    (W)[2] = *(const ulonglong2*)(wb + ((size_t)2 * nt + (j)) * 4);             \
    (W)[3] = *(const ulonglong2*)(wb + ((size_t)3 * nt + (j)) * 4);             \
    (W)[4] = *(const ulonglong2*)(wb + ((size_t)4 * nt + (j)) * 4);             \
    (D0) = prl[r0 * PSTR + (j)];                                                \
    (D1) = prl[r1 * PSTR + (j)];                                                \
} while (0)

// compute stage: 20-MAC dual-row, fold prefetched dst at the end, store
#define WCOMP(W, D0, D1, j) do {                                                \
    ull a0 = pack2(0.0f, 0.0f);                                                 \
    ull a1 = pack2(0.0f, 0.0f);                                                 \
    a0 = ffma2((W)[0].x, h0[0].x, a0); a1 = ffma2((W)[0].x, h1[0].x, a1);       \
    a0 = ffma2((W)[0].y, h0[0].y, a0); a1 = ffma2((W)[0].y, h1[0].y, a1);       \
    a0 = ffma2((W)[1].x, h0[1].x, a0); a1 = ffma2((W)[1].x, h1[1].x, a1);       \
    a0 = ffma2((W)[1].y, h0[1].y, a0); a1 = ffma2((W)[1].y, h1[1].y, a1);       \
    a0 = ffma2((W)[2].x, h0[2].x, a0); a1 = ffma2((W)[2].x, h1[2].x, a1);       \
    a0 = ffma2((W)[2].y, h0[2].y, a0); a1 = ffma2((W)[2].y, h1[2].y, a1);       \
    a0 = ffma2((W)[3].x, h0[3].x, a0); a1 = ffma2((W)[3].x, h1[3].x, a1);       \
    a0 = ffma2((W)[3].y, h0[3].y, a0); a1 = ffma2((W)[3].y, h1[3].y, a1);       \
    a0 = ffma2((W)[4].x, h0[4].x, a0); a1 = ffma2((W)[4].x, h1[4].x, a1);       \
    a0 = ffma2((W)[4].y, h0[4].y, a0); a1 = ffma2((W)[4].y, h1[4].y, a1);       \
    prl[r0 * PSTR + (j)] = hsum2(a0) + (D0);                                    \
    prl[r1 * PSTR + (j)] = hsum2(a1) + (D1);                                    \
} while (0)

__global__ void __launch_bounds__(T, 1)
net_kernel(const float* __restrict__ u, float* __restrict__ out)
{
    extern __shared__ float sm[];
    float* pre  = sm;                       // [5][8][PSTR]
    float* pre6 = pre + 5 * MROWS * PSTR;   // [8][P6STR]
    float* hbt  = pre6 + MROWS * P6STR;     // [5][8][20]
    float* usm  = hbt + 5 * 160;            // [8][64]
    float* wd   = usm + 512;                // [2020]
    float* sv   = wd + 2020;                // [8]

    const int tid  = threadIdx.x;
    const int lane = tid & 31;
    const int wid  = tid >> 5;
    const int pair = lane & 3;                   // row pair within warp
    const int r0 = 2 * pair, r1 = r0 + 1;
    const int lv  = wid & 3;                     // this warp's scatter level
    const int jw  = (wid >> 2) * 8 + (lane >> 2);// j-lane within level: 0..31
    const int jl  = tid >> 2;                    // legacy lane for fc6 (0..127)

    for (int k = tid; k < 5 * MROWS * PSTR; k += T) pre[k] = 0.0f;
    for (int k = tid; k < MROWS * P6STR; k += T) pre6[k] = 0.0f;
    {
        int ii = tid >> 3, rr = tid & 7;
        usm[rr * NS + ii] = u[(size_t)ii * BATCH + (size_t)blockIdx.x * MROWS + rr];
    }
    for (int k = tid; k < 2020; k += T) wd[k] = g_Wd[k];
    __syncthreads();

    for (int i = 0; i < NS; ++i) {
        // ===== diagonal chain: 160 threads (warps 0-4) =====
        if (tid < 160) {
            const int dr = tid / 20, dc = tid - (tid / 20) * 20;
            hbt[dr * 20 + dc] = sigmoidf(pre[dr * PSTR + i * HID + dc]);
            BAR_DIAG();
            #pragma unroll 1
            for (int dlv = 0; dlv < 4; ++dlv) {
                float acc = pre[((dlv + 1) * MROWS + dr) * PSTR + i * HID + dc];
                float acc2 = 0.0f;
                const float* w  = wd + dlv * 400 + dc;
                const float* hh = hbt + dlv * 160 + dr * 20;
                #pragma unroll
                for (int ci = 0; ci < 10; ++ci) {
                    acc  = fmaf(w[(2 * ci)     * 20], hh[2 * ci],     acc);
                    acc2 = fmaf(w[(2 * ci + 1) * 20], hh[2 * ci + 1], acc2);
                }
                hbt[(dlv + 1) * 160 + dr * 20 + dc] = sigmoidf(acc + acc2);
                BAR_DIAG();
            }
            if (tid < MROWS) {                           // fc6 diag + sample
                float acc = pre6[tid * P6STR + i];
                const float* hh = hbt + 4 * 160 + tid * 20;
                #pragma unroll
                for (int ci = 0; ci < 20; ++ci) acc = fmaf(wd[2000 + ci], hh[ci], acc);
                float x = sigmoidf(acc);
                out[((size_t)blockIdx.x * MROWS + tid) * NS + i] = x;
                sv[tid] = (x >= usm[tid * NS + i]) ? 1.0f : -1.0f;
            }
        }
        __syncthreads();

        // ===== scatter phase =====
        if (i < 63) {
            const int nso1 = 63 - i;
            const int nt = nso1 * HID;
            const int tbase = (i + 1) * HID;
            const size_t soff = (size_t)slab_off1(i);

            // fc2..fc5 — LEVEL-PER-WARP: each warp streams its whole level,
            // one long ping-ponged burst per step (one drain instead of four)
            {
                const float* wb = g_Ws4 + (size_t)lv * LVL + soff * 400;
                float* prl = pre + (size_t)(lv + 1) * MROWS * PSTR + tbase;
                ulonglong2 h0[5], h1[5];
                {
                    const ulonglong2* p0 = (const ulonglong2*)(hbt + lv * 160 + r0 * 20);
                    const ulonglong2* p1 = (const ulonglong2*)(hbt + lv * 160 + r1 * 20);
                    #pragma unroll
                    for (int q = 0; q < 5; ++q) { h0[q] = p0[q]; h1[q] = p1[q]; }
                }
                int j0 = jw;
                if (j0 < nt) {
                    ulonglong2 wA[5], wB[5];
                    float dA0, dA1, dB0, dB1;
                    WLOAD(wA, dA0, dA1, j0);
                    for (;;) {
                        int j1 = j0 + NJW;
                        if (j1 >= nt) { WCOMP(wA, dA0, dA1, j0); break; }
                        WLOAD(wB, dB0, dB1, j1);
                        WCOMP(wA, dA0, dA1, j0);
                        j0 = j1 + NJW;
                        if (j0 >= nt) { WCOMP(wB, dB0, dB1, j1); break; }
                        WLOAD(wA, dA0, dA1, j0);
                        WCOMP(wB, dB0, dB1, j1);
                    }
                }
            }
            // fc6 (single round, lanes jl < nso1)
            if (jl < nso1) {
                const float* wb6 = g_W6s + soff * 20;
                const ulonglong2* hp0 = (const ulonglong2*)(hbt + 4 * 160 + r0 * 20);
                const ulonglong2* hp1 = (const ulonglong2*)(hbt + 4 * 160 + r1 * 20);
                float* d0p = pre6 + r0 * P6STR + (i + 1 + jl);
                float* d1p = pre6 + r1 * P6STR + (i + 1 + jl);
                float dd0 = *d0p, dd1 = *d1p;
                ull a0 = pack2(0.0f, 0.0f), a1 = a0;
                #pragma unroll
                for (int k = 0; k < 5; ++k) {
                    ulonglong2 wv = *(const ulonglong2*)(wb6 + ((size_t)k * nso1 + jl) * 4);
                    ulonglong2 h0v = hp0[k], h1v = hp1[k];
                    a0 = ffma2(wv.x, h0v.x, a0); a0 = ffma2(wv.y, h0v.y, a0);
                    a1 = ffma2(wv.x, h1v.x, a1); a1 = ffma2(wv.y, h1v.y, a1);
                }
                *d0p = hsum2(a0) + dd0;
                *d1p = hsum2(a1) + dd1;
            }
            // fc1 rank-1
            {
                const float* wb1 = g_W1s + soff * 20;
                float* p1 = pre + tbase;
                float s0 = sv[0], s1 = sv[1], s2 = sv[2], s3 = sv[3];
                float s4 = sv[4], s5 = sv[5], s6 = sv[6], s7 = sv[7];
                for (int j = tid; j < nt; j += T) {
                    float w = wb1[j];
                    p1[0 * PSTR + j] += w * s0;  p1[1 * PSTR + j] += w * s1;
                    p1[2 * PSTR + j] += w * s2;  p1[3 * PSTR + j] += w * s3;
                    p1[4 * PSTR + j] += w * s4;  p1[5 * PSTR + j] += w * s5;
                    p1[6 * PSTR + j] += w * s6;  p1[7 * PSTR + j] += w * s7;
                }
            }
            // prefetch next step's diag weights
            {
                const float* src = g_Wd + (size_t)(i + 1) * 2020;
                for (int k = tid; k < 2020; k += T) wd[k] = src[k];
            }
        }
        __syncthreads();
    }
}

extern "C" void kernel_launch(void* const* d_in, const int* in_sizes, int n_in,
                              void* d_out, int out_size)
{
    (void)in_sizes; (void)n_in; (void)out_size;
    const float* u  = (const float*)d_in[1];
    const float* W1 = (const float*)d_in[2];
    const float* W2 = (const float*)d_in[3];
    const float* W3 = (const float*)d_in[4];
    const float* W4 = (const float*)d_in[5];
    const float* W5 = (const float*)d_in[6];
    const float* W6 = (const float*)d_in[7];
    float* out = (float*)d_out;

    dim3 pg(64, 6);
    prep_scatter<<<pg, 256>>>(W1, W2, W3, W4, W5, W6);

    const int smem_bytes = (5 * MROWS * PSTR + MROWS * P6STR + 5 * 160
                            + 512 + 2020 + 8) * (int)sizeof(float);   // ~221 KB
    cudaFuncSetAttribute(net_kernel, cudaFuncAttributeMaxDynamicSharedMemorySize, smem_bytes);
    net_kernel<<<BATCH / MROWS, T, smem_bytes>>>(u, out);
}

// round 13
// speedup vs baseline: 1.3478x; 1.1360x over previous
#include <cuda_runtime.h>
#include <math.h>

#define NS     64
#define HID    20
#define HDIM   1280
#define BATCH  16384
#define MROWS  8
#define T      384             // 12 warps = 4 levels x 3 warps, reg cap 168
#define NJW    48              // j-stride per level (3 warps x 16 j)
#define PSTR   1284
#define P6STR  68
#define LVL    806400          // 2016*400 floats per level

typedef unsigned long long ull;

// Chunk-major scatter weights (best measured layout):
//   slab si (nt=(63-si)*20 targets): float4 at [k*nt + j] = W[j][4k..4k+3]
__device__ float g_Ws4[4 * LVL];
__device__ float g_W1s[2016 * 20];      // fc1 scalar, j-major
__device__ float g_W6s[2016 * 20];      // fc6 chunk-major: (k, t) float4
__device__ float g_Wd [64 * 2020];      // diag per si: [lv*400 + ci*20 + c], fc6 at 2000

__device__ __forceinline__ int slab_off1(int si) { return 63 * si - (si * (si - 1)) / 2; }

__global__ void prep_scatter(const float* __restrict__ W1, const float* __restrict__ W2,
                             const float* __restrict__ W3, const float* __restrict__ W4,
                             const float* __restrict__ W5, const float* __restrict__ W6)
{
    const int si = blockIdx.x, what = blockIdx.y;
    const int nso1 = 63 - si;
    const int nt = nso1 * 20;
    if (what < 4) {
        const float* W = (what == 0) ? W2 : (what == 1) ? W3 : (what == 2) ? W4 : W5;
        float* dst = g_Ws4 + (size_t)what * LVL + (size_t)slab_off1(si) * 400;
        const int cnt = nso1 * 400;
        for (int t = threadIdx.x; t < cnt; t += blockDim.x) {
            int m = t & 3, q = t >> 2;
            int j = q % nt, k = q / nt;
            int so = si + 1 + j / 20, c = j % 20, ci = 4 * k + m;
            dst[t] = W[(size_t)(c * NS + so) * HDIM + ci * NS + si];
        }
    } else if (what == 4) {
        float* d1 = g_W1s + (size_t)slab_off1(si) * 20;
        for (int t = threadIdx.x; t < nt; t += blockDim.x) {
            int so = si + 1 + t / 20, c = t % 20;
            d1[t] = W1[(size_t)(c * NS + so) * NS + si];
        }
        float* dd = g_Wd + (size_t)si * 2020;
        for (int t = threadIdx.x; t < 2020; t += blockDim.x) {
            if (t < 1600) {
                int lv = t / 400, rem = t - lv * 400;
                int ci = rem / 20, c = rem - ci * 20;
                const float* W = (lv == 0) ? W2 : (lv == 1) ? W3 : (lv == 2) ? W4 : W5;
                dd[t] = W[(size_t)(c * NS + si) * HDIM + ci * NS + si];
            } else if (t < 2000) {
                dd[t] = 0.0f;
            } else {
                dd[t] = W6[(size_t)si * HDIM + (t - 2000) * NS + si];
            }
        }
    } else {
        float* d6 = g_W6s + (size_t)slab_off1(si) * 20;
        const int cnt = nso1 * 20;
        for (int t = threadIdx.x; t < cnt; t += blockDim.x) {
            int m = t & 3, q = t >> 2;
            int tt = q % nso1, k = q / nso1;
            int so = si + 1 + tt, ci = 4 * k + m;
            d6[t] = W6[(size_t)so * HDIM + ci * NS + si];
        }
    }
}

__device__ __forceinline__ ull ffma2(ull a, ull b, ull c)
{
    ull d;
    asm("fma.rn.f32x2 %0, %1, %2, %3;" : "=l"(d) : "l"(a), "l"(b), "l"(c));
    return d;
}
__device__ __forceinline__ ull pack2(float lo, float hi)
{
    ull v;
    asm("mov.b64 %0, {%1, %2};" : "=l"(v) : "f"(lo), "f"(hi));
    return v;
}
__device__ __forceinline__ float hsum2(ull v)
{
    float lo, hi;
    asm("mov.b64 {%0, %1}, %2;" : "=f"(lo), "=f"(hi) : "l"(v));
    return lo + hi;
}
__device__ __forceinline__ float sigmoidf(float x) { return 1.0f / (1.0f + expf(-x)); }

#define BAR_DIAG() asm volatile("bar.sync 1, 160;" ::: "memory")

// load 5 weight chunks (unique per 16 j within warp) + 4 dst accumulators
#define WLOAD4(W, D, j) do {                                                    \
    (W)[0] = *(const ulonglong2*)(wb + ((size_t)0 * nt + (j)) * 4);             \
    (W)[1] = *(const ulonglong2*)(wb + ((size_t)1 * nt + (j)) * 4);             \
    (W)[2] = *(const ulonglong2*)(wb + ((size_t)2 * nt + (j)) * 4);             \
    (W)[3] = *(const ulonglong2*)(wb + ((size_t)3 * nt + (j)) * 4);             \
    (W)[4] = *(const ulonglong2*)(wb + ((size_t)4 * nt + (j)) * 4);             \
    (D)[0] = prl[(rb + 0) * PSTR + (j)];                                        \
    (D)[1] = prl[(rb + 1) * PSTR + (j)];                                        \
    (D)[2] = prl[(rb + 2) * PSTR + (j)];                                        \
    (D)[3] = prl[(rb + 3) * PSTR + (j)];                                        \
} while (0)

// 80-MAC (4 rows x 20 ci) compute, fold prefetched dst, store
#define WCOMP4(W, D, j) do {                                                    \
    ull a0 = 0ull, a1 = 0ull, a2 = 0ull, a3 = 0ull;                             \
    _Pragma("unroll")                                                           \
    for (int k = 0; k < 5; ++k) {                                               \
        a0 = ffma2((W)[k].x, hh[0][k].x, a0);                                   \
        a1 = ffma2((W)[k].x, hh[1][k].x, a1);                                   \
        a2 = ffma2((W)[k].x, hh[2][k].x, a2);                                   \
        a3 = ffma2((W)[k].x, hh[3][k].x, a3);                                   \
        a0 = ffma2((W)[k].y, hh[0][k].y, a0);                                   \
        a1 = ffma2((W)[k].y, hh[1][k].y, a1);                                   \
        a2 = ffma2((W)[k].y, hh[2][k].y, a2);                                   \
        a3 = ffma2((W)[k].y, hh[3][k].y, a3);                                   \
    }                                                                           \
    prl[(rb + 0) * PSTR + (j)] = hsum2(a0) + (D)[0];                            \
    prl[(rb + 1) * PSTR + (j)] = hsum2(a1) + (D)[1];                            \
    prl[(rb + 2) * PSTR + (j)] = hsum2(a2) + (D)[2];                            \
    prl[(rb + 3) * PSTR + (j)] = hsum2(a3) + (D)[3];                            \
} while (0)

__global__ void __launch_bounds__(T, 1)
net_kernel(const float* __restrict__ u, float* __restrict__ out)
{
    extern __shared__ float sm[];
    float* pre  = sm;                       // [5][8][PSTR]
    float* pre6 = pre + 5 * MROWS * PSTR;   // [8][P6STR]
    float* hbt  = pre6 + MROWS * P6STR;     // [5][8][20]
    float* usm  = hbt + 5 * 160;            // [8][64]
    float* wd   = usm + 512;                // [2020]
    float* sv   = wd + 2020;                // [8]

    const int tid  = threadIdx.x;
    const int lane = tid & 31;
    const int wid  = tid >> 5;
    const int lv   = wid & 3;                    // this warp's scatter level
    const int wgrp = wid >> 2;                   // 0..2
    const int jw   = wgrp * 16 + (lane >> 1);    // j-lane within level: 0..47
    const int grp  = lane & 1;                   // row group (rows grp*4..grp*4+3)
    const int rb   = grp * 4;
    // fc6 lanes (2-row mapping, once per step)
    const int pair = tid & 3, jl = tid >> 2;
    const int r0 = 2 * pair, r1 = r0 + 1;

    for (int k = tid; k < 5 * MROWS * PSTR; k += T) pre[k] = 0.0f;
    for (int k = tid; k < MROWS * P6STR; k += T) pre6[k] = 0.0f;
    for (int k = tid; k < 512; k += T) {
        int ii = k >> 3, rr = k & 7;
        usm[rr * NS + ii] = u[(size_t)ii * BATCH + (size_t)blockIdx.x * MROWS + rr];
    }
    for (int k = tid; k < 2020; k += T) wd[k] = g_Wd[k];
    __syncthreads();

    for (int i = 0; i < NS; ++i) {
        // ===== diagonal chain: 160 threads (warps 0-4) =====
        if (tid < 160) {
            const int dr = tid / 20, dc = tid - (tid / 20) * 20;
            hbt[dr * 20 + dc] = sigmoidf(pre[dr * PSTR + i * HID + dc]);
            BAR_DIAG();
            #pragma unroll 1
            for (int dlv = 0; dlv < 4; ++dlv) {
                float acc = pre[((dlv + 1) * MROWS + dr) * PSTR + i * HID + dc];
                float acc2 = 0.0f;
                const float* w  = wd + dlv * 400 + dc;
                const float* hh_ = hbt + dlv * 160 + dr * 20;
                #pragma unroll
                for (int ci = 0; ci < 10; ++ci) {
                    acc  = fmaf(w[(2 * ci)     * 20], hh_[2 * ci],     acc);
                    acc2 = fmaf(w[(2 * ci + 1) * 20], hh_[2 * ci + 1], acc2);
                }
                hbt[(dlv + 1) * 160 + dr * 20 + dc] = sigmoidf(acc + acc2);
                BAR_DIAG();
            }
            if (tid < MROWS) {                           // fc6 diag + sample
                float acc = pre6[tid * P6STR + i];
                const float* hh_ = hbt + 4 * 160 + tid * 20;
                #pragma unroll
                for (int ci = 0; ci < 20; ++ci) acc = fmaf(wd[2000 + ci], hh_[ci], acc);
                float x = sigmoidf(acc);
                out[((size_t)blockIdx.x * MROWS + tid) * NS + i] = x;
                sv[tid] = (x >= usm[tid * NS + i]) ? 1.0f : -1.0f;
            }
        }
        __syncthreads();

        // ===== scatter phase =====
        if (i < 63) {
            const int nso1 = 63 - i;
            const int nt = nso1 * HID;
            const int tbase = (i + 1) * HID;
            const size_t soff = (size_t)slab_off1(i);

            // fc2..fc5 — level-per-warp, 4 rows per lane (16 distinct j per warp:
            // halves redundant L1 return bytes), 2-deep ping-pong on w+dst
            {
                const float* wb = g_Ws4 + (size_t)lv * LVL + soff * 400;
                float* prl = pre + (size_t)(lv + 1) * MROWS * PSTR + tbase;
                ulonglong2 hh[4][5];
                #pragma unroll
                for (int t = 0; t < 4; ++t) {
                    const ulonglong2* hp = (const ulonglong2*)(hbt + lv * 160 + (rb + t) * 20);
                    #pragma unroll
                    for (int q = 0; q < 5; ++q) hh[t][q] = hp[q];
                }
                int j0 = jw;
                if (j0 < nt) {
                    ulonglong2 wA[5], wB[5];
                    float dA[4], dB[4];
                    WLOAD4(wA, dA, j0);
                    for (;;) {
                        int j1 = j0 + NJW;
                        if (j1 >= nt) { WCOMP4(wA, dA, j0); break; }
                        WLOAD4(wB, dB, j1);
                        WCOMP4(wA, dA, j0);
                        j0 = j1 + NJW;
                        if (j0 >= nt) { WCOMP4(wB, dB, j1); break; }
                        WLOAD4(wA, dA, j0);
                        WCOMP4(wB, dB, j1);
                    }
                }
            }
            // fc6 (single round, lanes jl < nso1)
            if (jl < nso1) {
                const float* wb6 = g_W6s + soff * 20;
                const ulonglong2* hp0 = (const ulonglong2*)(hbt + 4 * 160 + r0 * 20);
                const ulonglong2* hp1 = (const ulonglong2*)(hbt + 4 * 160 + r1 * 20);
                float* d0p = pre6 + r0 * P6STR + (i + 1 + jl);
                float* d1p = pre6 + r1 * P6STR + (i + 1 + jl);
                float dd0 = *d0p, dd1 = *d1p;
                ull a0 = 0ull, a1 = 0ull;
                #pragma unroll
                for (int k = 0; k < 5; ++k) {
                    ulonglong2 wv = *(const ulonglong2*)(wb6 + ((size_t)k * nso1 + jl) * 4);
                    ulonglong2 h0v = hp0[k], h1v = hp1[k];
                    a0 = ffma2(wv.x, h0v.x, a0); a0 = ffma2(wv.y, h0v.y, a0);
                    a1 = ffma2(wv.x, h1v.x, a1); a1 = ffma2(wv.y, h1v.y, a1);
                }
                *d0p = hsum2(a0) + dd0;
                *d1p = hsum2(a1) + dd1;
            }
            // fc1 rank-1
            {
                const float* wb1 = g_W1s + soff * 20;
                float* p1 = pre + tbase;
                float s0 = sv[0], s1 = sv[1], s2 = sv[2], s3 = sv[3];
                float s4 = sv[4], s5 = sv[5], s6 = sv[6], s7 = sv[7];
                for (int j = tid; j < nt; j += T) {
                    float w = wb1[j];
                    p1[0 * PSTR + j] += w * s0;  p1[1 * PSTR + j] += w * s1;
                    p1[2 * PSTR + j] += w * s2;  p1[3 * PSTR + j] += w * s3;
                    p1[4 * PSTR + j] += w * s4;  p1[5 * PSTR + j] += w * s5;
                    p1[6 * PSTR + j] += w * s6;  p1[7 * PSTR + j] += w * s7;
                }
            }
            // prefetch next step's diag weights
            {
                const float* src = g_Wd + (size_t)(i + 1) * 2020;
                for (int k = tid; k < 2020; k += T) wd[k] = src[k];
            }
        }
        __syncthreads();
    }
}

extern "C" void kernel_launch(void* const* d_in, const int* in_sizes, int n_in,
                              void* d_out, int out_size)
{
    (void)in_sizes; (void)n_in; (void)out_size;
    const float* u  = (const float*)d_in[1];
    const float* W1 = (const float*)d_in[2];
    const float* W2 = (const float*)d_in[3];
    const float* W3 = (const float*)d_in[4];
    const float* W4 = (const float*)d_in[5];
    const float* W5 = (const float*)d_in[6];
    const float* W6 = (const float*)d_in[7];
    float* out = (float*)d_out;

    dim3 pg(64, 6);
    prep_scatter<<<pg, 256>>>(W1, W2, W3, W4, W5, W6);

    const int smem_bytes = (5 * MROWS * PSTR + MROWS * P6STR + 5 * 160
                            + 512 + 2020 + 8) * (int)sizeof(float);   // ~221 KB
    cudaFuncSetAttribute(net_kernel, cudaFuncAttributeMaxDynamicSharedMemorySize, smem_bytes);
    net_kernel<<<BATCH / MROWS, T, smem_bytes>>>(u, out);
}